// round 16
// baseline (speedup 1.0000x reference)
#include <cuda_runtime.h>
#include <cuda_fp16.h>
#include <cstdint>

#define T_TOK 8192
#define DDIM  1024
#define FDIM  4096
#define NEXP  8
#define LN_EPS 1e-5f
#define CVT_N4 (NEXP * DDIM * FDIM / 4)   // 8388608 float4 per weight tensor

// ---------------- scratch (static device globals; no allocations) ----------
__device__ __half g_Xh[(size_t)T_TOK * DDIM];   // layernormed tokens, fp16
__device__ __half g_Hh[(size_t)T_TOK * FDIM];   // expert hidden, fp16
__device__ __half g_W1h[(size_t)NEXP * DDIM * FDIM]; // W1 fp16 [E][D][F]
__device__ __half g_W2h[(size_t)NEXP * FDIM * DDIM]; // W2 fp16 [E][F][D]
__device__ int    g_perm[NEXP * T_TOK];
__device__ int    g_cnt[NEXP];
__device__ float  g_gate[T_TOK];

// ---------------------------------------------------------------------------
// fp32 -> fp16 convert for W1 only + zero g_cnt (W2 cvt rides inside GEMM1)
__global__ void cvt_w1_kernel(const float* __restrict__ W1,
                              __half* __restrict__ w1h) {
    if (blockIdx.x == 0 && threadIdx.x < NEXP) g_cnt[threadIdx.x] = 0;
    int i = blockIdx.x * blockDim.x + threadIdx.x;
    if (i >= CVT_N4) return;
    float4 v = reinterpret_cast<const float4*>(W1)[i];
    reinterpret_cast<__half2*>(w1h)[2 * i + 0] = __floats2half2_rn(v.x, v.y);
    reinterpret_cast<__half2*>(w1h)[2 * i + 1] = __floats2half2_rn(v.z, v.w);
}

// 2 tokens per 256-thread block (128 threads per token)  [R10-proven]
__global__ void router_ln_kernel(const float* __restrict__ x,
                                 const float* __restrict__ Wr,
                                 const float* __restrict__ br,
                                 const float* __restrict__ ln_g,
                                 const float* __restrict__ ln_b) {
    const int tid  = threadIdx.x;
    const int half = tid >> 7;          // 0 / 1
    const int htid = tid & 127;
    const int t    = blockIdx.x * 2 + half;
    const float* xr = x + (size_t)t * DDIM;

    float v[8];
    float sum = 0.f, sumsq = 0.f;
    float lg[8];
#pragma unroll
    for (int e = 0; e < 8; e++) lg[e] = 0.f;

#pragma unroll
    for (int k = 0; k < 8; k++) {
        const int d = htid + 128 * k;
        const float xv = xr[d];
        v[k] = xv;
        sum += xv;
        sumsq += xv * xv;
        const float4* w4 = reinterpret_cast<const float4*>(Wr + (size_t)d * 8);
        const float4 w0 = w4[0];
        const float4 w1 = w4[1];
        lg[0] += xv * w0.x; lg[1] += xv * w0.y; lg[2] += xv * w0.z; lg[3] += xv * w0.w;
        lg[4] += xv * w1.x; lg[5] += xv * w1.y; lg[6] += xv * w1.z; lg[7] += xv * w1.w;
    }

#pragma unroll
    for (int off = 16; off > 0; off >>= 1) {
        sum   += __shfl_xor_sync(0xffffffffu, sum, off);
        sumsq += __shfl_xor_sync(0xffffffffu, sumsq, off);
#pragma unroll
        for (int e = 0; e < 8; e++)
            lg[e] += __shfl_xor_sync(0xffffffffu, lg[e], off);
    }

    __shared__ float red[8][10];
    __shared__ float bc[2][2];
    const int lane = tid & 31, warp = tid >> 5;
    if (lane == 0) {
        red[warp][0] = sum;
        red[warp][1] = sumsq;
#pragma unroll
        for (int e = 0; e < 8; e++) red[warp][2 + e] = lg[e];
    }
    __syncthreads();

    if (htid == 0) {
        float s = 0.f, ss = 0.f, L[8];
#pragma unroll
        for (int e = 0; e < 8; e++) L[e] = 0.f;
#pragma unroll
        for (int w = half * 4; w < half * 4 + 4; w++) {
            s  += red[w][0];
            ss += red[w][1];
#pragma unroll
            for (int e = 0; e < 8; e++) L[e] += red[w][2 + e];
        }
        const float mu  = s * (1.0f / DDIM);
        const float var = ss * (1.0f / DDIM) - mu * mu;
        const float rstd = rsqrtf(var + LN_EPS);

        float lmax = -3.4e38f;
        int idx = 0;
#pragma unroll
        for (int e = 0; e < 8; e++) {
            const float le = L[e] + br[e];
            if (le > lmax) { lmax = le; idx = e; }   // first-max wins
        }
        float denom = 0.f;
#pragma unroll
        for (int e = 0; e < 8; e++) denom += expf(L[e] + br[e] - lmax);
        const float gate = 1.0f / denom;

        const int slot = atomicAdd(&g_cnt[idx], 1);
        g_perm[idx * T_TOK + slot] = t;
        g_gate[t] = gate;
        bc[half][0] = mu;
        bc[half][1] = rstd;
    }
    __syncthreads();

    const float mu = bc[half][0], rstd = bc[half][1];
#pragma unroll
    for (int k = 0; k < 8; k++) {
        const int d = htid + 128 * k;
        g_Xh[(size_t)t * DDIM + d] =
            __float2half_rn((v[k] - mu) * rstd * ln_g[d] + ln_b[d]);
    }
}

// ---------------------------------------------------------------------------
__device__ __forceinline__ void cp_async16(void* dst, const void* src, int srcsz) {
    uint32_t d = (uint32_t)__cvta_generic_to_shared(dst);
    asm volatile("cp.async.cg.shared.global [%0], [%1], 16, %2;\n"
                 :: "r"(d), "l"(src), "r"(srcsz));
}
__device__ __forceinline__ void ldsm_x4(uint32_t& r0, uint32_t& r1,
                                        uint32_t& r2, uint32_t& r3,
                                        const void* p) {
    uint32_t a = (uint32_t)__cvta_generic_to_shared(p);
    asm volatile("ldmatrix.sync.aligned.m8n8.x4.shared.b16 {%0,%1,%2,%3}, [%4];"
                 : "=r"(r0), "=r"(r1), "=r"(r2), "=r"(r3) : "r"(a));
}
__device__ __forceinline__ void ldsm_x4t(uint32_t& r0, uint32_t& r1,
                                         uint32_t& r2, uint32_t& r3,
                                         const void* p) {
    uint32_t a = (uint32_t)__cvta_generic_to_shared(p);
    asm volatile("ldmatrix.sync.aligned.m8n8.x4.trans.shared.b16 {%0,%1,%2,%3}, [%4];"
                 : "=r"(r0), "=r"(r1), "=r"(r2), "=r"(r3) : "r"(a));
}
__device__ __forceinline__ void mma_f16(float c[4], const uint32_t a[4],
                                        const uint32_t b[2]) {
    asm volatile(
        "mma.sync.aligned.m16n8k16.row.col.f32.f16.f16.f32 "
        "{%0,%1,%2,%3}, {%4,%5,%6,%7}, {%8,%9}, {%0,%1,%2,%3};\n"
        : "+f"(c[0]), "+f"(c[1]), "+f"(c[2]), "+f"(c[3])
        : "r"(a[0]), "r"(a[1]), "r"(a[2]), "r"(a[3]), "r"(b[0]), "r"(b[1]));
}
__device__ __forceinline__ void mbar_init(uint32_t addr, uint32_t count) {
    asm volatile("mbarrier.init.shared.b64 [%0], %1;" :: "r"(addr), "r"(count)
                 : "memory");
}
__device__ __forceinline__ void mbar_wait(uint32_t addr, uint32_t parity) {
    asm volatile(
        "{\n\t.reg .pred P1;\n\t"
        "WAIT_LOOP_%=:\n\t"
        "mbarrier.try_wait.parity.acquire.cta.shared::cta.b64 P1, [%0], %1, 0x989680;\n\t"
        "@P1 bra.uni WAIT_DONE_%=;\n\t"
        "bra.uni WAIT_LOOP_%=;\n\t"
        "WAIT_DONE_%=:\n\t}"
        :: "r"(addr), "r"(parity) : "memory");
}
__device__ __forceinline__ void mbar_arrive(uint32_t addr) {
    asm volatile("mbarrier.arrive.shared.b64 _, [%0];" :: "r"(addr) : "memory");
}
__device__ __forceinline__ void cp_async_arrive(uint32_t addr) {
    asm volatile("cp.async.mbarrier.arrive.noinc.shared.b64 [%0];"
                 :: "r"(addr) : "memory");
}

// Geometry: 128x256 CTA tile, 512 threads (16 warps, warp tile 64x32), KC=32,
// NSTAGE=4, 1 CTA/SM (16 warps/SM preserved vs R15's 2x8).
#define TILE_N 256
#define A_STRIDE 40    // 32 k-halves + 8 pad = 80B rows (proven)
#define B_STRIDE 264   // 256 n-halves + 8 pad = 528B rows (same 4-bank walk)
#define A_STG (128 * A_STRIDE)  // 5120 halves
#define B_STG (32 * B_STRIDE)   // 8448 halves
#define NSTAGE 4
#define DATA_HALVES (NSTAGE * (A_STG + B_STG))            // 54272 halves
#define GEMM_SMEM (DATA_HALVES * 2 + 2 * NSTAGE * 8)      // 108608 B

// Grouped expert GEMM, fp16 operands, fp32 accum, mbarrier-staged pipeline
// (R12/R14-winning). 128x256 tile halves B/A global traffic per FLOP.
// FIRST=true additionally carries piggyback blocks (blockIdx.z == NEXP) that
// convert W2 fp32->fp16 concurrently with GEMM1 compute.
template <int KD, int ND, bool FIRST>
__global__ __launch_bounds__(512, 1)
void moe_gemm_kernel(const __half* __restrict__ Bsrc,
                     const float* __restrict__ bias,
                     float* __restrict__ OutParam,
                     const float* __restrict__ CvtSrc,   // W2 fp32 (GEMM1 only)
                     __half* __restrict__ CvtDst) {      // W2 fp16 (GEMM1 only)
    const int tid = threadIdx.x;

    if (FIRST && blockIdx.z == NEXP) {
        // ---- piggyback: grid-strided W2 convert ----
        const int nthr = gridDim.x * gridDim.y * 512;
        int i = (blockIdx.y * gridDim.x + blockIdx.x) * 512 + tid;
        for (; i < CVT_N4; i += nthr) {
            float4 v = reinterpret_cast<const float4*>(CvtSrc)[i];
            reinterpret_cast<__half2*>(CvtDst)[2 * i + 0] = __floats2half2_rn(v.x, v.y);
            reinterpret_cast<__half2*>(CvtDst)[2 * i + 1] = __floats2half2_rn(v.z, v.w);
        }
        return;
    }

    const int e   = blockIdx.z;
    const int cnt = g_cnt[e];
    const int m0  = blockIdx.y * 128;
    if (m0 >= cnt) return;
    const int n0  = blockIdx.x * TILE_N;

    const __half* Asrc = FIRST ? g_Xh : g_Hh;

    extern __shared__ __half smem[];
    __half* Asm = smem;                   // [NSTAGE][128][A_STRIDE]
    __half* Bsm = smem + NSTAGE * A_STG;  // [NSTAGE][32][B_STRIDE]
    uint32_t mb;
    {
        uint32_t sb;
        asm("{ .reg .u64 t; cvta.to.shared.u64 t, %1; cvt.u32.u64 %0, t; }"
            : "=r"(sb) : "l"((void*)smem));
        mb = sb + DATA_HALVES * 2;        // barrier block at end of data
    }
    const uint32_t FULL = mb;             // full[s]  (count 512)
    const uint32_t FREE = mb + NSTAGE * 8; // free[s] (count 16: lane0/warp)

    if (tid == 0) {
#pragma unroll
        for (int s = 0; s < NSTAGE; s++) {
            mbar_init(FULL + 8 * s, 512);
            mbar_init(FREE + 8 * s, 16);
        }
    }
    __syncthreads();

    // A loads: 4 threads per row (128 rows), 1 chunk of 16B each (32 halves/row)
    const int rA = tid >> 2;
    const int cA = tid & 3;
    const int gmA = m0 + rA;
    const int tokA = (gmA < cnt) ? g_perm[e * T_TOK + gmA] : -1;
    const __half* a_srcp = (tokA >= 0) ? Asrc + (size_t)tokA * KD : Asrc;
    const int a_ok = (tokA >= 0) ? 16 : 0;
    // B loads: 16 threads per row (32 rows), 2 chunks of 16B each (256 halves/row)
    const int rB = tid >> 4;
    const int cB = (tid & 15) * 2;
    const __half* Bbase = Bsrc + (size_t)e * KD * ND + n0;

    const int warp = tid >> 5, lane = tid & 31;
    const int wm = (warp >> 3) * 64;   // 0 / 64
    const int wn = (warp & 7) * 32;    // 0..224

    float acc[4][4][4];
#pragma unroll
    for (int mi = 0; mi < 4; mi++)
#pragma unroll
        for (int ni = 0; ni < 4; ni++)
#pragma unroll
            for (int r = 0; r < 4; r++) acc[mi][ni][r] = 0.f;

    auto load_A = [&](int kt, int buf) {
        const int kbase = kt * 32;
        __half* adst = Asm + buf * A_STG + rA * A_STRIDE + cA * 8;
        const __half* asrc = a_srcp + kbase + cA * 8;
        cp_async16(adst, asrc, a_ok);
    };
    auto load_B = [&](int kt, int buf) {
        const int kbase = kt * 32;
        __half* bdst = Bsm + buf * B_STG + rB * B_STRIDE + cB * 8;
        const __half* bsrc = Bbase + (size_t)(kbase + rB) * ND + cB * 8;
        cp_async16(bdst,     bsrc,     16);
        cp_async16(bdst + 8, bsrc + 8, 16);
    };

    constexpr int KT = KD / 32;
    // prologue: fill stages 0..NSTAGE-2 (fresh buffers, no free-wait needed)
#pragma unroll
    for (int s = 0; s < NSTAGE - 1; s++) {
        load_A(s, s);
        load_B(s, s);
        cp_async_arrive(FULL + 8 * s);
    }

    uint32_t fullph = 0, freeph = 0;   // per-stage phase parity bitmasks

    for (int kt = 0; kt < KT; kt++) {
        const int buf = kt & (NSTAGE - 1);
        const bool have_next = (kt + NSTAGE - 1 < KT);
        const int nbuf = (kt + NSTAGE - 1) & (NSTAGE - 1);

        // RAW: stage data landed
        mbar_wait(FULL + 8 * buf, (fullph >> buf) & 1);
        fullph ^= 1u << buf;

        const __half* Ab = Asm + buf * A_STG;
        const __half* Bb = Bsm + buf * B_STG;

        // ---- ks group 0 ----
        uint32_t afr[4][4];
#pragma unroll
        for (int mi = 0; mi < 4; mi++) {
            const int row = wm + mi * 16 + (lane & 15);
            const int col = (lane >> 4) * 8;
            ldsm_x4(afr[mi][0], afr[mi][1], afr[mi][2], afr[mi][3],
                    Ab + row * A_STRIDE + col);
        }
        uint32_t bfr[4][2];
#pragma unroll
        for (int pr = 0; pr < 2; pr++) {
            const int row = (lane & 15);
            const int col = wn + pr * 16 + (lane >> 4) * 8;
            ldsm_x4t(bfr[2 * pr][0], bfr[2 * pr][1],
                     bfr[2 * pr + 1][0], bfr[2 * pr + 1][1],
                     Bb + row * B_STRIDE + col);
        }
        // WAR: nbuf was consumed at epoch kt-1; wait all warps released it.
        if (have_next) {
            if (kt > 0) {
                mbar_wait(FREE + 8 * nbuf, (freeph >> nbuf) & 1);
                freeph ^= 1u << nbuf;
            }
            load_A(kt + NSTAGE - 1, nbuf);
        }
#pragma unroll
        for (int mi = 0; mi < 4; mi++)
#pragma unroll
            for (int ni = 0; ni < 4; ni++)
                mma_f16(acc[mi][ni], afr[mi], bfr[ni]);

        // ---- ks group 1 ----
#pragma unroll
        for (int mi = 0; mi < 4; mi++) {
            const int row = wm + mi * 16 + (lane & 15);
            const int col = 16 + (lane >> 4) * 8;
            ldsm_x4(afr[mi][0], afr[mi][1], afr[mi][2], afr[mi][3],
                    Ab + row * A_STRIDE + col);
        }
#pragma unroll
        for (int pr = 0; pr < 2; pr++) {
            const int row = 16 + (lane & 15);
            const int col = wn + pr * 16 + (lane >> 4) * 8;
            ldsm_x4t(bfr[2 * pr][0], bfr[2 * pr][1],
                     bfr[2 * pr + 1][0], bfr[2 * pr + 1][1],
                     Bb + row * B_STRIDE + col);
        }
        // warp's reads of buf complete -> ONE arrive per warp releases buffer
        if (lane == 0) mbar_arrive(FREE + 8 * buf);
        if (have_next) {
            load_B(kt + NSTAGE - 1, nbuf);
            cp_async_arrive(FULL + 8 * nbuf);
        }
#pragma unroll
        for (int mi = 0; mi < 4; mi++)
#pragma unroll
            for (int ni = 0; ni < 4; ni++)
                mma_f16(acc[mi][ni], afr[mi], bfr[ni]);
    }

    // epilogue
    const float* bvec = bias + (size_t)e * ND + n0;
#pragma unroll
    for (int mi = 0; mi < 4; mi++) {
#pragma unroll
        for (int r = 0; r < 2; r++) {
            const int row = wm + mi * 16 + (lane >> 2) + r * 8;
            const int gm = m0 + row;
            if (gm >= cnt) continue;
            const int tok = g_perm[e * T_TOK + gm];
            if (FIRST) {
                __half* orow = g_Hh + (size_t)tok * ND + n0;
#pragma unroll
                for (int ni = 0; ni < 4; ni++) {
                    const int ccol = wn + ni * 8 + (lane & 3) * 2;
                    float v0 = fmaxf(acc[mi][ni][r * 2 + 0] + bvec[ccol], 0.f);
                    float v1 = fmaxf(acc[mi][ni][r * 2 + 1] + bvec[ccol + 1], 0.f);
                    *reinterpret_cast<__half2*>(&orow[ccol]) =
                        __floats2half2_rn(v0, v1);
                }
            } else {
                const float gscale = g_gate[tok];
                float* orow = OutParam + (size_t)tok * ND + n0;
#pragma unroll
                for (int ni = 0; ni < 4; ni++) {
                    const int ccol = wn + ni * 8 + (lane & 3) * 2;
                    float v0 = (acc[mi][ni][r * 2 + 0] + bvec[ccol]) * gscale;
                    float v1 = (acc[mi][ni][r * 2 + 1] + bvec[ccol + 1]) * gscale;
                    *reinterpret_cast<float2*>(&orow[ccol]) = make_float2(v0, v1);
                }
            }
        }
    }
}

// ---------------------------------------------------------------------------
extern "C" void kernel_launch(void* const* d_in, const int* in_sizes, int n_in,
                              void* d_out, int out_size) {
    const float* x    = (const float*)d_in[0];
    const float* Wr   = (const float*)d_in[1];
    const float* br   = (const float*)d_in[2];
    const float* ln_g = (const float*)d_in[3];
    const float* ln_b = (const float*)d_in[4];
    const float* W1   = (const float*)d_in[5];
    const float* b1   = (const float*)d_in[6];
    const float* W2   = (const float*)d_in[7];
    const float* b2   = (const float*)d_in[8];
    float* out = (float*)d_out;

    const size_t smem = GEMM_SMEM;  // 108608 B
    cudaFuncSetAttribute(moe_gemm_kernel<DDIM, FDIM, true>,
                         cudaFuncAttributeMaxDynamicSharedMemorySize, (int)smem);
    cudaFuncSetAttribute(moe_gemm_kernel<FDIM, DDIM, false>,
                         cudaFuncAttributeMaxDynamicSharedMemorySize, (int)smem);

    __half* w1h;  cudaGetSymbolAddress((void**)&w1h, g_W1h);
    __half* w2h;  cudaGetSymbolAddress((void**)&w2h, g_W2h);

    // W1 convert + cnt zero (W2 convert piggybacks on GEMM1)
    cvt_w1_kernel<<<(CVT_N4 + 255) / 256, 256>>>(W1, w1h);

    router_ln_kernel<<<T_TOK / 2, 256>>>(x, Wr, br, ln_g, ln_b);

    // GEMM1 with one extra z-slice of W2-convert blocks
    dim3 g1(FDIM / TILE_N, T_TOK / 128, NEXP + 1);
    moe_gemm_kernel<DDIM, FDIM, true><<<g1, 512, smem>>>(w1h, b1, nullptr, W2, w2h);

    dim3 g2(DDIM / TILE_N, T_TOK / 128, NEXP);
    moe_gemm_kernel<FDIM, DDIM, false><<<g2, 512, smem>>>(w2h, b2, out, nullptr, nullptr);
}

// round 17
// speedup vs baseline: 1.0322x; 1.0322x over previous
#include <cuda_runtime.h>
#include <cuda_fp16.h>
#include <cstdint>

#define T_TOK 8192
#define DDIM  1024
#define FDIM  4096
#define NEXP  8
#define LN_EPS 1e-5f
#define CVT_N4 (NEXP * DDIM * FDIM / 4)   // 8388608 float4 per weight tensor

// ---------------- scratch (static device globals; no allocations) ----------
__device__ __half g_Xh[(size_t)T_TOK * DDIM];   // layernormed tokens, fp16
__device__ __half g_Hh[(size_t)T_TOK * FDIM];   // expert hidden, fp16
__device__ __half g_W1h[(size_t)NEXP * DDIM * FDIM]; // W1 fp16 [E][D][F]
__device__ __half g_W2h[(size_t)NEXP * FDIM * DDIM]; // W2 fp16 [E][F][D]
__device__ int    g_perm[NEXP * T_TOK];
__device__ int    g_cnt[NEXP];
__device__ float  g_gate[T_TOK];

// ---------------------------------------------------------------------------
// fp32 -> fp16 convert for W1 only + zero g_cnt (W2 cvt rides inside GEMM1)
__global__ void cvt_w1_kernel(const float* __restrict__ W1,
                              __half* __restrict__ w1h) {
    if (blockIdx.x == 0 && threadIdx.x < NEXP) g_cnt[threadIdx.x] = 0;
    int i = blockIdx.x * blockDim.x + threadIdx.x;
    if (i >= CVT_N4) return;
    float4 v = reinterpret_cast<const float4*>(W1)[i];
    reinterpret_cast<__half2*>(w1h)[2 * i + 0] = __floats2half2_rn(v.x, v.y);
    reinterpret_cast<__half2*>(w1h)[2 * i + 1] = __floats2half2_rn(v.z, v.w);
}

// 2 tokens per 256-thread block (128 threads per token)  [R10-proven]
__global__ void router_ln_kernel(const float* __restrict__ x,
                                 const float* __restrict__ Wr,
                                 const float* __restrict__ br,
                                 const float* __restrict__ ln_g,
                                 const float* __restrict__ ln_b) {
    const int tid  = threadIdx.x;
    const int half = tid >> 7;          // 0 / 1
    const int htid = tid & 127;
    const int t    = blockIdx.x * 2 + half;
    const float* xr = x + (size_t)t * DDIM;

    float v[8];
    float sum = 0.f, sumsq = 0.f;
    float lg[8];
#pragma unroll
    for (int e = 0; e < 8; e++) lg[e] = 0.f;

#pragma unroll
    for (int k = 0; k < 8; k++) {
        const int d = htid + 128 * k;
        const float xv = xr[d];
        v[k] = xv;
        sum += xv;
        sumsq += xv * xv;
        const float4* w4 = reinterpret_cast<const float4*>(Wr + (size_t)d * 8);
        const float4 w0 = w4[0];
        const float4 w1 = w4[1];
        lg[0] += xv * w0.x; lg[1] += xv * w0.y; lg[2] += xv * w0.z; lg[3] += xv * w0.w;
        lg[4] += xv * w1.x; lg[5] += xv * w1.y; lg[6] += xv * w1.z; lg[7] += xv * w1.w;
    }

#pragma unroll
    for (int off = 16; off > 0; off >>= 1) {
        sum   += __shfl_xor_sync(0xffffffffu, sum, off);
        sumsq += __shfl_xor_sync(0xffffffffu, sumsq, off);
#pragma unroll
        for (int e = 0; e < 8; e++)
            lg[e] += __shfl_xor_sync(0xffffffffu, lg[e], off);
    }

    __shared__ float red[8][10];
    __shared__ float bc[2][2];
    const int lane = tid & 31, warp = tid >> 5;
    if (lane == 0) {
        red[warp][0] = sum;
        red[warp][1] = sumsq;
#pragma unroll
        for (int e = 0; e < 8; e++) red[warp][2 + e] = lg[e];
    }
    __syncthreads();

    if (htid == 0) {
        float s = 0.f, ss = 0.f, L[8];
#pragma unroll
        for (int e = 0; e < 8; e++) L[e] = 0.f;
#pragma unroll
        for (int w = half * 4; w < half * 4 + 4; w++) {
            s  += red[w][0];
            ss += red[w][1];
#pragma unroll
            for (int e = 0; e < 8; e++) L[e] += red[w][2 + e];
        }
        const float mu  = s * (1.0f / DDIM);
        const float var = ss * (1.0f / DDIM) - mu * mu;
        const float rstd = rsqrtf(var + LN_EPS);

        float lmax = -3.4e38f;
        int idx = 0;
#pragma unroll
        for (int e = 0; e < 8; e++) {
            const float le = L[e] + br[e];
            if (le > lmax) { lmax = le; idx = e; }   // first-max wins
        }
        float denom = 0.f;
#pragma unroll
        for (int e = 0; e < 8; e++) denom += expf(L[e] + br[e] - lmax);
        const float gate = 1.0f / denom;

        const int slot = atomicAdd(&g_cnt[idx], 1);
        g_perm[idx * T_TOK + slot] = t;
        g_gate[t] = gate;
        bc[half][0] = mu;
        bc[half][1] = rstd;
    }
    __syncthreads();

    const float mu = bc[half][0], rstd = bc[half][1];
#pragma unroll
    for (int k = 0; k < 8; k++) {
        const int d = htid + 128 * k;
        g_Xh[(size_t)t * DDIM + d] =
            __float2half_rn((v[k] - mu) * rstd * ln_g[d] + ln_b[d]);
    }
}

// ---------------------------------------------------------------------------
__device__ __forceinline__ void cp_async16(void* dst, const void* src, int srcsz) {
    uint32_t d = (uint32_t)__cvta_generic_to_shared(dst);
    asm volatile("cp.async.cg.shared.global [%0], [%1], 16, %2;\n"
                 :: "r"(d), "l"(src), "r"(srcsz));
}
__device__ __forceinline__ void ldsm_x4(uint32_t& r0, uint32_t& r1,
                                        uint32_t& r2, uint32_t& r3,
                                        const void* p) {
    uint32_t a = (uint32_t)__cvta_generic_to_shared(p);
    asm volatile("ldmatrix.sync.aligned.m8n8.x4.shared.b16 {%0,%1,%2,%3}, [%4];"
                 : "=r"(r0), "=r"(r1), "=r"(r2), "=r"(r3) : "r"(a));
}
__device__ __forceinline__ void ldsm_x4t(uint32_t& r0, uint32_t& r1,
                                         uint32_t& r2, uint32_t& r3,
                                         const void* p) {
    uint32_t a = (uint32_t)__cvta_generic_to_shared(p);
    asm volatile("ldmatrix.sync.aligned.m8n8.x4.trans.shared.b16 {%0,%1,%2,%3}, [%4];"
                 : "=r"(r0), "=r"(r1), "=r"(r2), "=r"(r3) : "r"(a));
}
__device__ __forceinline__ void mma_f16(float c[4], const uint32_t a[4],
                                        const uint32_t b[2]) {
    asm volatile(
        "mma.sync.aligned.m16n8k16.row.col.f32.f16.f16.f32 "
        "{%0,%1,%2,%3}, {%4,%5,%6,%7}, {%8,%9}, {%0,%1,%2,%3};\n"
        : "+f"(c[0]), "+f"(c[1]), "+f"(c[2]), "+f"(c[3])
        : "r"(a[0]), "r"(a[1]), "r"(a[2]), "r"(a[3]), "r"(b[0]), "r"(b[1]));
}
__device__ __forceinline__ void mbar_init(uint32_t addr, uint32_t count) {
    asm volatile("mbarrier.init.shared.b64 [%0], %1;" :: "r"(addr), "r"(count)
                 : "memory");
}
__device__ __forceinline__ void mbar_wait(uint32_t addr, uint32_t parity) {
    asm volatile(
        "{\n\t.reg .pred P1;\n\t"
        "WAIT_LOOP_%=:\n\t"
        "mbarrier.try_wait.parity.acquire.cta.shared::cta.b64 P1, [%0], %1, 0x989680;\n\t"
        "@P1 bra.uni WAIT_DONE_%=;\n\t"
        "bra.uni WAIT_LOOP_%=;\n\t"
        "WAIT_DONE_%=:\n\t}"
        :: "r"(addr), "r"(parity) : "memory");
}
__device__ __forceinline__ void mbar_arrive(uint32_t addr) {
    asm volatile("mbarrier.arrive.shared.b64 _, [%0];" :: "r"(addr) : "memory");
}
__device__ __forceinline__ void cp_async_arrive(uint32_t addr) {
    asm volatile("cp.async.mbarrier.arrive.noinc.shared.b64 [%0];"
                 :: "r"(addr) : "memory");
}

// ===================== GEMM-A: 128x128 tile, 256 thr (R15-measured best for GEMM1)
#define A_STRIDE 40   // 32 k-halves + 8 pad = 80B rows
#define B_STRIDE 136  // 128 n-halves + 8 pad = 272B rows
#define A_STG (128 * A_STRIDE)  // 5120 halves
#define B_STG (32 * B_STRIDE)   // 4352 halves
#define NSTAGE 4
#define DATA_HALVES (NSTAGE * (A_STG + B_STG))            // 37888 halves
#define GEMM_SMEM (DATA_HALVES * 2 + 2 * NSTAGE * 8)      // 75840 B

template <int KD, int ND, bool FIRST>
__global__ __launch_bounds__(256, 2)
void moe_gemm_kernel(const __half* __restrict__ Bsrc,
                     const float* __restrict__ bias,
                     float* __restrict__ OutParam,
                     const float* __restrict__ CvtSrc,   // W2 fp32 (GEMM1 only)
                     __half* __restrict__ CvtDst) {      // W2 fp16 (GEMM1 only)
    const int tid = threadIdx.x;

    if (FIRST && blockIdx.z == NEXP) {
        // ---- piggyback: grid-strided W2 convert ----
        const int nthr = gridDim.x * gridDim.y * 256;
        int i = (blockIdx.y * gridDim.x + blockIdx.x) * 256 + tid;
        for (; i < CVT_N4; i += nthr) {
            float4 v = reinterpret_cast<const float4*>(CvtSrc)[i];
            reinterpret_cast<__half2*>(CvtDst)[2 * i + 0] = __floats2half2_rn(v.x, v.y);
            reinterpret_cast<__half2*>(CvtDst)[2 * i + 1] = __floats2half2_rn(v.z, v.w);
        }
        return;
    }

    const int e   = blockIdx.z;
    const int cnt = g_cnt[e];
    const int m0  = blockIdx.y * 128;
    if (m0 >= cnt) return;
    const int n0  = blockIdx.x * 128;

    const __half* Asrc = FIRST ? g_Xh : g_Hh;

    extern __shared__ __half smem[];
    __half* Asm = smem;                   // [NSTAGE][128][A_STRIDE]
    __half* Bsm = smem + NSTAGE * A_STG;  // [NSTAGE][32][B_STRIDE]
    uint32_t mb;
    {
        uint32_t sb;
        asm("{ .reg .u64 t; cvta.to.shared.u64 t, %1; cvt.u32.u64 %0, t; }"
            : "=r"(sb) : "l"((void*)smem));
        mb = sb + DATA_HALVES * 2;
    }
    const uint32_t FULL = mb;
    const uint32_t FREE = mb + NSTAGE * 8;

    if (tid == 0) {
#pragma unroll
        for (int s = 0; s < NSTAGE; s++) {
            mbar_init(FULL + 8 * s, 256);
            mbar_init(FREE + 8 * s, 8);
        }
    }
    __syncthreads();

    const int rA = tid >> 1;
    const int cA = (tid & 1) * 2;
    const int gmA = m0 + rA;
    const int tokA = (gmA < cnt) ? g_perm[e * T_TOK + gmA] : -1;
    const __half* a_srcp = (tokA >= 0) ? Asrc + (size_t)tokA * KD : Asrc;
    const int a_ok = (tokA >= 0) ? 16 : 0;
    const int rB = tid >> 3;
    const int cB = (tid & 7) * 2;
    const __half* Bbase = Bsrc + (size_t)e * KD * ND + n0;

    const int warp = tid >> 5, lane = tid & 31;
    const int wm = (warp >> 2) * 64;
    const int wn = (warp & 3) * 32;

    float acc[4][4][4];
#pragma unroll
    for (int mi = 0; mi < 4; mi++)
#pragma unroll
        for (int ni = 0; ni < 4; ni++)
#pragma unroll
            for (int r = 0; r < 4; r++) acc[mi][ni][r] = 0.f;

    auto load_A = [&](int kt, int buf) {
        const int kbase = kt * 32;
        __half* adst = Asm + buf * A_STG + rA * A_STRIDE + cA * 8;
        const __half* asrc = a_srcp + kbase + cA * 8;
        cp_async16(adst,      asrc,     a_ok);
        cp_async16(adst + 8,  asrc + 8, a_ok);
    };
    auto load_B = [&](int kt, int buf) {
        const int kbase = kt * 32;
        __half* bdst = Bsm + buf * B_STG + rB * B_STRIDE + cB * 8;
        const __half* bsrc = Bbase + (size_t)(kbase + rB) * ND + cB * 8;
        cp_async16(bdst,     bsrc,     16);
        cp_async16(bdst + 8, bsrc + 8, 16);
    };

    constexpr int KT = KD / 32;
#pragma unroll
    for (int s = 0; s < NSTAGE - 1; s++) {
        load_A(s, s);
        load_B(s, s);
        cp_async_arrive(FULL + 8 * s);
    }

    uint32_t fullph = 0, freeph = 0;

    for (int kt = 0; kt < KT; kt++) {
        const int buf = kt & (NSTAGE - 1);
        const bool have_next = (kt + NSTAGE - 1 < KT);
        const int nbuf = (kt + NSTAGE - 1) & (NSTAGE - 1);

        mbar_wait(FULL + 8 * buf, (fullph >> buf) & 1);
        fullph ^= 1u << buf;

        const __half* Ab = Asm + buf * A_STG;
        const __half* Bb = Bsm + buf * B_STG;

        uint32_t afr[4][4];
#pragma unroll
        for (int mi = 0; mi < 4; mi++) {
            const int row = wm + mi * 16 + (lane & 15);
            const int col = (lane >> 4) * 8;
            ldsm_x4(afr[mi][0], afr[mi][1], afr[mi][2], afr[mi][3],
                    Ab + row * A_STRIDE + col);
        }
        uint32_t bfr[4][2];
#pragma unroll
        for (int pr = 0; pr < 2; pr++) {
            const int row = (lane & 15);
            const int col = wn + pr * 16 + (lane >> 4) * 8;
            ldsm_x4t(bfr[2 * pr][0], bfr[2 * pr][1],
                     bfr[2 * pr + 1][0], bfr[2 * pr + 1][1],
                     Bb + row * B_STRIDE + col);
        }
        if (have_next) {
            if (kt > 0) {
                mbar_wait(FREE + 8 * nbuf, (freeph >> nbuf) & 1);
                freeph ^= 1u << nbuf;
            }
            load_A(kt + NSTAGE - 1, nbuf);
        }
#pragma unroll
        for (int mi = 0; mi < 4; mi++)
#pragma unroll
            for (int ni = 0; ni < 4; ni++)
                mma_f16(acc[mi][ni], afr[mi], bfr[ni]);

#pragma unroll
        for (int mi = 0; mi < 4; mi++) {
            const int row = wm + mi * 16 + (lane & 15);
            const int col = 16 + (lane >> 4) * 8;
            ldsm_x4(afr[mi][0], afr[mi][1], afr[mi][2], afr[mi][3],
                    Ab + row * A_STRIDE + col);
        }
#pragma unroll
        for (int pr = 0; pr < 2; pr++) {
            const int row = 16 + (lane & 15);
            const int col = wn + pr * 16 + (lane >> 4) * 8;
            ldsm_x4t(bfr[2 * pr][0], bfr[2 * pr][1],
                     bfr[2 * pr + 1][0], bfr[2 * pr + 1][1],
                     Bb + row * B_STRIDE + col);
        }
        if (lane == 0) mbar_arrive(FREE + 8 * buf);
        if (have_next) {
            load_B(kt + NSTAGE - 1, nbuf);
            cp_async_arrive(FULL + 8 * nbuf);
        }
#pragma unroll
        for (int mi = 0; mi < 4; mi++)
#pragma unroll
            for (int ni = 0; ni < 4; ni++)
                mma_f16(acc[mi][ni], afr[mi], bfr[ni]);
    }

    const float* bvec = bias + (size_t)e * ND + n0;
#pragma unroll
    for (int mi = 0; mi < 4; mi++) {
#pragma unroll
        for (int r = 0; r < 2; r++) {
            const int row = wm + mi * 16 + (lane >> 2) + r * 8;
            const int gm = m0 + row;
            if (gm >= cnt) continue;
            const int tok = g_perm[e * T_TOK + gm];
            if (FIRST) {
                __half* orow = g_Hh + (size_t)tok * ND + n0;
#pragma unroll
                for (int ni = 0; ni < 4; ni++) {
                    const int ccol = wn + ni * 8 + (lane & 3) * 2;
                    float v0 = fmaxf(acc[mi][ni][r * 2 + 0] + bvec[ccol], 0.f);
                    float v1 = fmaxf(acc[mi][ni][r * 2 + 1] + bvec[ccol + 1], 0.f);
                    *reinterpret_cast<__half2*>(&orow[ccol]) =
                        __floats2half2_rn(v0, v1);
                }
            } else {
                const float gscale = g_gate[tok];
                float* orow = OutParam + (size_t)tok * ND + n0;
#pragma unroll
                for (int ni = 0; ni < 4; ni++) {
                    const int ccol = wn + ni * 8 + (lane & 3) * 2;
                    float v0 = (acc[mi][ni][r * 2 + 0] + bvec[ccol]) * gscale;
                    float v1 = (acc[mi][ni][r * 2 + 1] + bvec[ccol + 1]) * gscale;
                    *reinterpret_cast<float2*>(&orow[ccol]) = make_float2(v0, v1);
                }
            }
        }
    }
}

// ===================== GEMM-B: 128x256 tile, 512 thr (R16-measured best for GEMM2)
#define TILE_N2 256
#define B2_STRIDE 264   // 256 n-halves + 8 pad = 528B rows
#define A2_STG (128 * A_STRIDE)   // 5120 halves
#define B2_STG (32 * B2_STRIDE)   // 8448 halves
#define DATA2_HALVES (NSTAGE * (A2_STG + B2_STG))          // 54272 halves
#define GEMM2_SMEM (DATA2_HALVES * 2 + 2 * NSTAGE * 8)     // 108608 B

template <int KD, int ND, bool FIRST>
__global__ __launch_bounds__(512, 1)
void moe_gemm256_kernel(const __half* __restrict__ Bsrc,
                        const float* __restrict__ bias,
                        float* __restrict__ OutParam) {
    const int tid = threadIdx.x;
    const int e   = blockIdx.z;
    const int cnt = g_cnt[e];
    const int m0  = blockIdx.y * 128;
    if (m0 >= cnt) return;
    const int n0  = blockIdx.x * TILE_N2;

    const __half* Asrc = FIRST ? g_Xh : g_Hh;

    extern __shared__ __half smem[];
    __half* Asm = smem;                    // [NSTAGE][128][A_STRIDE]
    __half* Bsm = smem + NSTAGE * A2_STG;  // [NSTAGE][32][B2_STRIDE]
    uint32_t mb;
    {
        uint32_t sb;
        asm("{ .reg .u64 t; cvta.to.shared.u64 t, %1; cvt.u32.u64 %0, t; }"
            : "=r"(sb) : "l"((void*)smem));
        mb = sb + DATA2_HALVES * 2;
    }
    const uint32_t FULL = mb;
    const uint32_t FREE = mb + NSTAGE * 8;

    if (tid == 0) {
#pragma unroll
        for (int s = 0; s < NSTAGE; s++) {
            mbar_init(FULL + 8 * s, 512);
            mbar_init(FREE + 8 * s, 16);
        }
    }
    __syncthreads();

    const int rA = tid >> 2;
    const int cA = tid & 3;
    const int gmA = m0 + rA;
    const int tokA = (gmA < cnt) ? g_perm[e * T_TOK + gmA] : -1;
    const __half* a_srcp = (tokA >= 0) ? Asrc + (size_t)tokA * KD : Asrc;
    const int a_ok = (tokA >= 0) ? 16 : 0;
    const int rB = tid >> 4;
    const int cB = (tid & 15) * 2;
    const __half* Bbase = Bsrc + (size_t)e * KD * ND + n0;

    const int warp = tid >> 5, lane = tid & 31;
    const int wm = (warp >> 3) * 64;
    const int wn = (warp & 7) * 32;

    float acc[4][4][4];
#pragma unroll
    for (int mi = 0; mi < 4; mi++)
#pragma unroll
        for (int ni = 0; ni < 4; ni++)
#pragma unroll
            for (int r = 0; r < 4; r++) acc[mi][ni][r] = 0.f;

    auto load_A = [&](int kt, int buf) {
        const int kbase = kt * 32;
        __half* adst = Asm + buf * A2_STG + rA * A_STRIDE + cA * 8;
        const __half* asrc = a_srcp + kbase + cA * 8;
        cp_async16(adst, asrc, a_ok);
    };
    auto load_B = [&](int kt, int buf) {
        const int kbase = kt * 32;
        __half* bdst = Bsm + buf * B2_STG + rB * B2_STRIDE + cB * 8;
        const __half* bsrc = Bbase + (size_t)(kbase + rB) * ND + cB * 8;
        cp_async16(bdst,     bsrc,     16);
        cp_async16(bdst + 8, bsrc + 8, 16);
    };

    constexpr int KT = KD / 32;
#pragma unroll
    for (int s = 0; s < NSTAGE - 1; s++) {
        load_A(s, s);
        load_B(s, s);
        cp_async_arrive(FULL + 8 * s);
    }

    uint32_t fullph = 0, freeph = 0;

    for (int kt = 0; kt < KT; kt++) {
        const int buf = kt & (NSTAGE - 1);
        const bool have_next = (kt + NSTAGE - 1 < KT);
        const int nbuf = (kt + NSTAGE - 1) & (NSTAGE - 1);

        mbar_wait(FULL + 8 * buf, (fullph >> buf) & 1);
        fullph ^= 1u << buf;

        const __half* Ab = Asm + buf * A2_STG;
        const __half* Bb = Bsm + buf * B2_STG;

        uint32_t afr[4][4];
#pragma unroll
        for (int mi = 0; mi < 4; mi++) {
            const int row = wm + mi * 16 + (lane & 15);
            const int col = (lane >> 4) * 8;
            ldsm_x4(afr[mi][0], afr[mi][1], afr[mi][2], afr[mi][3],
                    Ab + row * A_STRIDE + col);
        }
        uint32_t bfr[4][2];
#pragma unroll
        for (int pr = 0; pr < 2; pr++) {
            const int row = (lane & 15);
            const int col = wn + pr * 16 + (lane >> 4) * 8;
            ldsm_x4t(bfr[2 * pr][0], bfr[2 * pr][1],
                     bfr[2 * pr + 1][0], bfr[2 * pr + 1][1],
                     Bb + row * B2_STRIDE + col);
        }
        if (have_next) {
            if (kt > 0) {
                mbar_wait(FREE + 8 * nbuf, (freeph >> nbuf) & 1);
                freeph ^= 1u << nbuf;
            }
            load_A(kt + NSTAGE - 1, nbuf);
        }
#pragma unroll
        for (int mi = 0; mi < 4; mi++)
#pragma unroll
            for (int ni = 0; ni < 4; ni++)
                mma_f16(acc[mi][ni], afr[mi], bfr[ni]);

#pragma unroll
        for (int mi = 0; mi < 4; mi++) {
            const int row = wm + mi * 16 + (lane & 15);
            const int col = 16 + (lane >> 4) * 8;
            ldsm_x4(afr[mi][0], afr[mi][1], afr[mi][2], afr[mi][3],
                    Ab + row * A_STRIDE + col);
        }
#pragma unroll
        for (int pr = 0; pr < 2; pr++) {
            const int row = 16 + (lane & 15);
            const int col = wn + pr * 16 + (lane >> 4) * 8;
            ldsm_x4t(bfr[2 * pr][0], bfr[2 * pr][1],
                     bfr[2 * pr + 1][0], bfr[2 * pr + 1][1],
                     Bb + row * B2_STRIDE + col);
        }
        if (lane == 0) mbar_arrive(FREE + 8 * buf);
        if (have_next) {
            load_B(kt + NSTAGE - 1, nbuf);
            cp_async_arrive(FULL + 8 * nbuf);
        }
#pragma unroll
        for (int mi = 0; mi < 4; mi++)
#pragma unroll
            for (int ni = 0; ni < 4; ni++)
                mma_f16(acc[mi][ni], afr[mi], bfr[ni]);
    }

    const float* bvec = bias + (size_t)e * ND + n0;
#pragma unroll
    for (int mi = 0; mi < 4; mi++) {
#pragma unroll
        for (int r = 0; r < 2; r++) {
            const int row = wm + mi * 16 + (lane >> 2) + r * 8;
            const int gm = m0 + row;
            if (gm >= cnt) continue;
            const int tok = g_perm[e * T_TOK + gm];
            if (FIRST) {
                __half* orow = g_Hh + (size_t)tok * ND + n0;
#pragma unroll
                for (int ni = 0; ni < 4; ni++) {
                    const int ccol = wn + ni * 8 + (lane & 3) * 2;
                    float v0 = fmaxf(acc[mi][ni][r * 2 + 0] + bvec[ccol], 0.f);
                    float v1 = fmaxf(acc[mi][ni][r * 2 + 1] + bvec[ccol + 1], 0.f);
                    *reinterpret_cast<__half2*>(&orow[ccol]) =
                        __floats2half2_rn(v0, v1);
                }
            } else {
                const float gscale = g_gate[tok];
                float* orow = OutParam + (size_t)tok * ND + n0;
#pragma unroll
                for (int ni = 0; ni < 4; ni++) {
                    const int ccol = wn + ni * 8 + (lane & 3) * 2;
                    float v0 = (acc[mi][ni][r * 2 + 0] + bvec[ccol]) * gscale;
                    float v1 = (acc[mi][ni][r * 2 + 1] + bvec[ccol + 1]) * gscale;
                    *reinterpret_cast<float2*>(&orow[ccol]) = make_float2(v0, v1);
                }
            }
        }
    }
}

// ---------------------------------------------------------------------------
extern "C" void kernel_launch(void* const* d_in, const int* in_sizes, int n_in,
                              void* d_out, int out_size) {
    const float* x    = (const float*)d_in[0];
    const float* Wr   = (const float*)d_in[1];
    const float* br   = (const float*)d_in[2];
    const float* ln_g = (const float*)d_in[3];
    const float* ln_b = (const float*)d_in[4];
    const float* W1   = (const float*)d_in[5];
    const float* b1   = (const float*)d_in[6];
    const float* W2   = (const float*)d_in[7];
    const float* b2   = (const float*)d_in[8];
    float* out = (float*)d_out;

    cudaFuncSetAttribute(moe_gemm_kernel<DDIM, FDIM, true>,
                         cudaFuncAttributeMaxDynamicSharedMemorySize, GEMM_SMEM);
    cudaFuncSetAttribute(moe_gemm256_kernel<FDIM, DDIM, false>,
                         cudaFuncAttributeMaxDynamicSharedMemorySize, GEMM2_SMEM);

    __half* w1h;  cudaGetSymbolAddress((void**)&w1h, g_W1h);
    __half* w2h;  cudaGetSymbolAddress((void**)&w2h, g_W2h);

    // W1 convert + cnt zero (W2 convert piggybacks on GEMM1)
    cvt_w1_kernel<<<(CVT_N4 + 255) / 256, 256>>>(W1, w1h);

    router_ln_kernel<<<T_TOK / 2, 256>>>(x, Wr, br, ln_g, ln_b);

    // GEMM1: 128x128 kernel (R15-measured best) + W2-convert piggyback slice
    dim3 g1(FDIM / 128, T_TOK / 128, NEXP + 1);
    moe_gemm_kernel<DDIM, FDIM, true><<<g1, 256, GEMM_SMEM>>>(w1h, b1, nullptr, W2, w2h);

    // GEMM2: 128x256 kernel (R16-measured best)
    dim3 g2(DDIM / TILE_N2, T_TOK / 128, NEXP);
    moe_gemm256_kernel<FDIM, DDIM, false><<<g2, 512, GEMM2_SMEM>>>(w2h, b2, out);
}